// round 15
// baseline (speedup 1.0000x reference)
#include <cuda_runtime.h>
#include <math.h>

#define N_   10000
#define P_   2000
#define CT_  10
#define E_   320000
#define DAE0 100
#define DAE1 20
#define GAE0 32
#define GAE1 20
#define FCAT 40
#define FEAT 64

#define D1_R     32
#define D1_PAIRS 16
#define D1_KC    250
#define D1_NC    8      // P_ / D1_KC

typedef unsigned long long u64;

// ---------------- scratch (no allocs allowed) ----------------
__device__ __align__(16) float g_h1[N_*DAE0];
__device__ __align__(16) float g_h1p[D1_NC][N_*DAE0];   // dense1 k-split partials
__device__ __align__(16) float g_feat[N_*FCAT];
__device__ __align__(16) float g_deg[N_];
__device__ __align__(16) float g_dinv[N_];
__device__ __align__(16) float g_coef[E_];
__device__ __align__(16) float g_hW1[N_*GAE0];
__device__ __align__(16) float g_h[N_*GAE0];
__device__ __align__(16) float g_hWm[N_*GAE1];
__device__ __align__(16) float g_hWs[N_*GAE1];
__device__ __align__(16) float g_mu[N_*GAE1];
__device__ __align__(16) float g_ls[N_*GAE1];
__device__ __align__(16) float g_zg[N_*FEAT];
__device__ double g_acc[3];   // pos_sum, neg_sum, kl_sum

// ---------------- f32x2 helpers ----------------
__device__ __forceinline__ u64 pk2(float lo, float hi) {
    u64 r;
    asm("mov.b64 %0, {%1, %2};" : "=l"(r) : "r"(__float_as_uint(lo)), "r"(__float_as_uint(hi)));
    return r;
}
__device__ __forceinline__ u64 dup2(float v) { return pk2(v, v); }
__device__ __forceinline__ void unpk(u64 v, float& lo, float& hi) {
    unsigned a, b;
    asm("mov.b64 {%0, %1}, %2;" : "=r"(a), "=r"(b) : "l"(v));
    lo = __uint_as_float(a); hi = __uint_as_float(b);
}
__device__ __forceinline__ u64 fma2(u64 a, u64 b, u64 c) {
    u64 d;
    asm("fma.rn.f32x2 %0, %1, %2, %3;" : "=l"(d) : "l"(a), "l"(b), "l"(c));
    return d;
}
__device__ __forceinline__ float celu_f(float v) { return v > 0.f ? v : expm1f(v); }

__device__ __forceinline__ void block_add(double* target, float v) {
    #pragma unroll
    for (int o = 16; o > 0; o >>= 1) v += __shfl_down_sync(0xffffffffu, v, o);
    __shared__ float ws[8];
    int w = threadIdx.x >> 5;
    if ((threadIdx.x & 31) == 0) ws[w] = v;
    __syncthreads();
    if (threadIdx.x == 0) {
        float s = 0.f;
        int nw = (blockDim.x + 31) >> 5;
        for (int i = 0; i < nw; i++) s += ws[i];
        atomicAdd(target, (double)s);
    }
}

// ---------------- kernels ----------------
__global__ void k_deg_init() {
    int i = blockIdx.x * blockDim.x + threadIdx.x;
    if (i < N_) g_deg[i] = 1.f;
}
__global__ void k_acc_zero() {
    if (threadIdx.x < 3) g_acc[threadIdx.x] = 0.0;
}
__global__ void k_deg_acc(const int* __restrict__ ei, const float* __restrict__ ew) {
    int e = blockIdx.x * blockDim.x + threadIdx.x;
    if (e < E_) atomicAdd(&g_deg[ei[E_ + e]], ew[e]);
}
__global__ void k_dinv() {
    int i = blockIdx.x * blockDim.x + threadIdx.x;
    if (i < N_) g_dinv[i] = rsqrtf(g_deg[i]);
}
__global__ void k_coef(const int* __restrict__ ei, const float* __restrict__ ew) {
    int e = blockIdx.x * blockDim.x + threadIdx.x;
    if (e < E_) g_coef[e] = g_dinv[ei[e]] * g_dinv[ei[E_ + e]] * ew[e];
}

// dense1 partial: 32 rows (16 reg row-pairs) x 250-k chunk; 2 output cols/thread.
// block = 64 threads (50 compute lanes: thread t owns cols 2t, 2t+1).
__global__ void __launch_bounds__(64) k_dense1p(const float* __restrict__ x,
                                                const float* __restrict__ W1) {
    __shared__ u64 sx[D1_PAIRS * D1_KC];   // 32 KB
    int r0 = blockIdx.x * D1_R;
    int c0 = blockIdx.y * D1_KC;
    for (int idx = threadIdx.x; idx < D1_PAIRS * D1_KC; idx += 64) {
        int p = idx / D1_KC, k = idx - p * D1_KC;
        int ra = r0 + 2 * p;
        int rb = ra + 1;
        if (ra > N_ - 1) ra = N_ - 1;
        if (rb > N_ - 1) rb = N_ - 1;
        sx[idx] = pk2(x[(size_t)ra * P_ + c0 + k], x[(size_t)rb * P_ + c0 + k]);
    }
    __syncthreads();
    int t = threadIdx.x;
    if (t >= 50) return;
    int j = t * 2;
    u64 accA[D1_PAIRS], accB[D1_PAIRS];
    #pragma unroll
    for (int p = 0; p < D1_PAIRS; p++) { accA[p] = 0ull; accB[p] = 0ull; }
    const float* w = W1 + (size_t)c0 * DAE0 + j;
    #pragma unroll 2
    for (int k = 0; k < D1_KC; k++) {
        float2 wv = *(const float2*)(w + (size_t)k * DAE0);
        u64 wa = dup2(wv.x);
        u64 wb = dup2(wv.y);
        #pragma unroll
        for (int p = 0; p < D1_PAIRS; p++) {
            u64 s = sx[p * D1_KC + k];
            accA[p] = fma2(s, wa, accA[p]);
            accB[p] = fma2(s, wb, accB[p]);
        }
    }
    float* outp = g_h1p[blockIdx.y];
    #pragma unroll
    for (int p = 0; p < D1_PAIRS; p++) {
        float loA, hiA, loB, hiB;
        unpk(accA[p], loA, hiA);
        unpk(accB[p], loB, hiB);
        int ra = r0 + 2 * p;
        if (ra < N_)     *(float2*)(outp + (size_t)ra * DAE0 + j)       = make_float2(loA, loB);
        if (ra + 1 < N_) *(float2*)(outp + (size_t)(ra + 1) * DAE0 + j) = make_float2(hiA, hiB);
    }
}

// dense1 finalize: h1 = celu(sum_partials + bias)
__global__ void k_dense1f(const float* __restrict__ b1) {
    int idx = blockIdx.x * blockDim.x + threadIdx.x;
    if (idx >= N_ * DAE0) return;
    int j = idx % DAE0;
    float s = b1[j];
    #pragma unroll
    for (int c = 0; c < D1_NC; c++) s += g_h1p[c][idx];
    g_h1[idx] = celu_f(s);
}

// feat[:,0:20] = celu(h1 @ W2 + b2)
__global__ void k_dense2(const float* __restrict__ W2, const float* __restrict__ b2) {
    int idx = blockIdx.x * blockDim.x + threadIdx.x;
    if (idx >= N_ * DAE1) return;
    int n = idx / DAE1, j = idx - n * DAE1;
    float acc = b2[j];
    const float* h = g_h1 + n * DAE0;
    #pragma unroll 4
    for (int k = 0; k < DAE0; k++) acc += h[k] * W2[k * DAE1 + j];
    g_feat[n * FCAT + j] = celu_f(acc);
}

// hW1 = feat_x @ Wf   [N,20]x[20,32]
__global__ void k_hW1(const float* __restrict__ Wf) {
    int idx = blockIdx.x * blockDim.x + threadIdx.x;
    if (idx >= N_ * GAE0) return;
    int n = idx >> 5, f = idx & 31;
    float acc = 0.f;
    const float* fr = g_feat + n * FCAT;
    #pragma unroll
    for (int k = 0; k < DAE1; k++) acc += fr[k] * Wf[k * GAE0 + f];
    g_hW1[idx] = acc;
}

__global__ void k_gcn_init_h(const float* __restrict__ bf) {
    int idx = blockIdx.x * blockDim.x + threadIdx.x;
    if (idx >= N_ * GAE0) return;
    int n = idx >> 5;
    float di = g_dinv[n];
    g_h[idx] = di * di * g_hW1[idx] + bf[idx & 31];
}
__global__ void k_gcn_edge_h(const int* __restrict__ ei) {
    int idx = blockIdx.x * blockDim.x + threadIdx.x;
    if (idx >= E_ * GAE0) return;
    int e = idx >> 5, f = idx & 31;
    int s = ei[e], d = ei[E_ + e];
    atomicAdd(g_h + d * GAE0 + f, g_coef[e] * g_hW1[s * GAE0 + f]);
}

__global__ void k_mls(const float* __restrict__ Wm, const float* __restrict__ Ws) {
    int idx = blockIdx.x * blockDim.x + threadIdx.x;
    if (idx >= N_ * GAE1) return;
    int n = idx / GAE1, f = idx - n * GAE1;
    float am = 0.f, as = 0.f;
    const float* h = g_h + n * GAE0;
    #pragma unroll
    for (int k = 0; k < GAE0; k++) {
        float rh = fmaxf(h[k], 0.f);
        am += rh * Wm[k * GAE1 + f];
        as += rh * Ws[k * GAE1 + f];
    }
    g_hWm[idx] = am;
    g_hWs[idx] = as;
}

__global__ void k_gcn_init_muls(const float* __restrict__ bm, const float* __restrict__ bs) {
    int idx = blockIdx.x * blockDim.x + threadIdx.x;
    if (idx >= N_ * GAE1) return;
    int n = idx / GAE1, f = idx - n * GAE1;
    float di = g_dinv[n];
    float d2 = di * di;
    g_mu[idx] = d2 * g_hWm[idx] + bm[f];
    g_ls[idx] = d2 * g_hWs[idx] + bs[f];
}
__global__ void k_gcn_edge_muls(const int* __restrict__ ei) {
    int idx = blockIdx.x * blockDim.x + threadIdx.x;
    if (idx >= E_ * GAE1) return;
    int e = idx / GAE1, f = idx - e * GAE1;
    int s = ei[e], d = ei[E_ + e];
    float c = g_coef[e];
    atomicAdd(g_mu + d * GAE1 + f, c * g_hWm[s * GAE1 + f]);
    atomicAdd(g_ls + d * GAE1 + f, c * g_hWs[s * GAE1 + f]);
}

__global__ void k_finalize(const float* __restrict__ eps) {
    int idx = blockIdx.x * blockDim.x + threadIdx.x;
    float t = 0.f;
    if (idx < N_ * GAE1) {
        int n = idx / GAE1, j = idx - n * GAE1;
        float m = g_mu[idx];
        float l = fminf(g_ls[idx], 10.f);
        float el = expf(l);
        g_feat[n * FCAT + DAE1 + j] = m + eps[idx] * el;
        t = 1.f + 2.f * l - m * m - el * el;
    }
    block_add(&g_acc[2], t);
}

__global__ void __launch_bounds__(320) k_ct(const float* __restrict__ Wc,
                                            const float* __restrict__ bc,
                                            float* __restrict__ out) {
    __shared__ float fs[32 * FCAT];
    __shared__ float sv[32][CT_];
    int rbase = blockIdx.x * 32;
    for (int i = threadIdx.x; i < 32 * FCAT; i += 320) {
        int gi = rbase * FCAT + i;
        fs[i] = (gi < N_ * FCAT) ? g_feat[gi] : 0.f;
    }
    __syncthreads();
    int rl = threadIdx.x / CT_, c = threadIdx.x - rl * CT_;
    float acc = bc[c];
    const float* fr = fs + rl * FCAT;
    #pragma unroll
    for (int k = 0; k < FCAT; k++) acc += fr[k] * Wc[k * CT_ + c];
    float v = fmaxf(acc, 0.f);
    sv[rl][c] = v;
    __syncthreads();
    float s = 0.f;
    #pragma unroll
    for (int cc = 0; cc < CT_; cc++) s += sv[rl][cc];
    int n = rbase + rl;
    if (n < N_) out[n * CT_ + c] = v / (s + 1e-6f);
}

__global__ void k_zg(const float* __restrict__ Wg, const float* __restrict__ bg) {
    int idx = blockIdx.x * blockDim.x + threadIdx.x;
    if (idx >= N_ * FEAT) return;
    int n = idx >> 6, j = idx & 63;
    float acc = bg[j];
    const float* fr = g_feat + n * FCAT;
    #pragma unroll
    for (int k = 0; k < FCAT; k++) acc += fr[k] * Wg[k * FEAT + j];
    g_zg[idx] = fmaxf(acc, 0.f);
}

__global__ void __launch_bounds__(256) k_edge_loss(const int* __restrict__ ei,
                                                   const int* __restrict__ nei,
                                                   const float* __restrict__ ew) {
    int gid = blockIdx.x * 256 + threadIdx.x;
    int oct = gid >> 3, l8 = gid & 7;
    bool pos = oct < E_;
    int e = pos ? oct : oct - E_;
    const int* arr = pos ? ei : nei;
    int s = arr[e], d = arr[E_ + e];
    const float4* za = (const float4*)(g_zg + s * FEAT + l8 * 8);
    const float4* zb = (const float4*)(g_zg + d * FEAT + l8 * 8);
    float4 a0 = za[0], a1 = za[1], b0 = zb[0], b1 = zb[1];
    float dot = a0.x*b0.x + a0.y*b0.y + a0.z*b0.z + a0.w*b0.w
              + a1.x*b1.x + a1.y*b1.y + a1.z*b1.z + a1.w*b1.w;
    dot += __shfl_down_sync(0xffffffffu, dot, 4, 8);
    dot += __shfl_down_sync(0xffffffffu, dot, 2, 8);
    dot += __shfl_down_sync(0xffffffffu, dot, 1, 8);
    float val = 0.f;
    if (l8 == 0) {
        float sg = 1.f / (1.f + expf(-dot));
        if (pos) { float df = sg - ew[e]; val = df * df; }
        else     { val = sg * sg; }
    }
    block_add(&g_acc[pos ? 0 : 1], val);
}

__global__ void k_gae(float* __restrict__ out) {
    double kl_factor = -0.5 / ((double)N_ * (double)N_);
    out[0] = (float)(g_acc[0] / (double)E_ + g_acc[1] / (double)E_ + kl_factor * g_acc[2]);
}

__global__ void __launch_bounds__(256) k_xdec(const float* __restrict__ Wdec,
                                              const float* __restrict__ bdec,
                                              float* __restrict__ out) {
    __shared__ u64 fd[16 * FCAT];
    int rbase = blockIdx.y * 16;
    for (int i = threadIdx.x; i < 16 * FCAT; i += 256)
        fd[i] = dup2(g_feat[rbase * FCAT + i]);
    __syncthreads();
    int j2 = blockIdx.x * 256 + threadIdx.x;
    if (j2 >= P_ / 2) return;
    u64 wv[FCAT];
    const float* wb = Wdec + 2 * j2;
    #pragma unroll
    for (int k = 0; k < FCAT; k++) wv[k] = *(const u64*)(wb + k * P_);
    u64 bb = *(const u64*)(bdec + 2 * j2);
    for (int r = 0; r < 16; r++) {
        u64 a0 = bb, a1 = 0ull;
        const u64* fr = fd + r * FCAT;
        #pragma unroll
        for (int k = 0; k < FCAT; k += 2) {
            a0 = fma2(fr[k],     wv[k],     a0);
            a1 = fma2(fr[k + 1], wv[k + 1], a1);
        }
        float l0, h0, l1, h1;
        unpk(a0, l0, h0); unpk(a1, l1, h1);
        float2 res = make_float2(l0 + l1, h0 + h1);
        *(float2*)(out + (size_t)(rbase + r) * P_ + 2 * j2) = res;
    }
}

// pw head: 64x160 tile, 128 threads, 8 rows/thread (16 groups x 8 rowslots).
__global__ void __launch_bounds__(128) k_pw(const float* __restrict__ Wv,
                                            const float* __restrict__ bv,
                                            float* __restrict__ out) {
    __shared__ float sm[64 * 160];           // 40KB
    int g  = threadIdx.x & 15;
    int rs = threadIdx.x >> 4;               // 0..7
    int rbase = blockIdx.y * 64;
    int cbase = blockIdx.x * 160;
    for (int i = threadIdx.x; i < 64 * FCAT; i += 128) {
        int gi = rbase * FCAT + i;
        sm[i] = (gi < N_ * FCAT) ? g_feat[gi] : 0.f;
    }
    __syncthreads();

    u64 acc[8][5];
    #pragma unroll
    for (int r = 0; r < 8; r++)
        #pragma unroll
        for (int c = 0; c < 5; c++) acc[r][c] = 0ull;

    const float* wbase = Wv + cbase + g * CT_;
    int r0 = rs * 8;
    #pragma unroll 2
    for (int k = 0; k < FCAT; k++) {
        const u64* wp = (const u64*)(wbase + (size_t)k * (P_ * CT_));
        u64 w0 = wp[0], w1 = wp[1], w2 = wp[2], w3 = wp[3], w4 = wp[4];
        #pragma unroll
        for (int r = 0; r < 8; r++) {
            u64 d = dup2(sm[(r0 + r) * FCAT + k]);
            acc[r][0] = fma2(d, w0, acc[r][0]);
            acc[r][1] = fma2(d, w1, acc[r][1]);
            acc[r][2] = fma2(d, w2, acc[r][2]);
            acc[r][3] = fma2(d, w3, acc[r][3]);
            acc[r][4] = fma2(d, w4, acc[r][4]);
        }
    }
    __syncthreads();

    float bvv[CT_];
    #pragma unroll
    for (int c = 0; c < CT_; c++) bvv[c] = bv[cbase + g * CT_ + c];

    #pragma unroll
    for (int r = 0; r < 8; r++) {
        float v[CT_];
        #pragma unroll
        for (int cp = 0; cp < 5; cp++) unpk(acc[r][cp], v[2*cp], v[2*cp+1]);
        float s = 0.f;
        #pragma unroll
        for (int c = 0; c < CT_; c++) { v[c] = fmaxf(v[c] + bvv[c], 0.f); s += v[c]; }
        float inv = 1.f / (s + 1e-6f);
        #pragma unroll
        for (int c = 0; c < CT_; c++) sm[(r0 + r) * 160 + g * CT_ + c] = v[c] * inv;
    }
    __syncthreads();
    for (int i = threadIdx.x; i < 64 * 160; i += 128) {
        int rl = i / 160, cl = i - rl * 160;
        int row = rbase + rl;
        if (row < N_) out[(size_t)row * (P_ * CT_) + cbase + cl] = sm[i];
    }
}

// ---------------- launch ----------------
extern "C" void kernel_launch(void* const* d_in, const int* in_sizes, int n_in,
                              void* d_out, int out_size) {
    const float* x    = (const float*)d_in[0];
    const float* ew   = (const float*)d_in[1];
    const float* eps  = (const float*)d_in[2];
    const float* W1   = (const float*)d_in[3];
    const float* b1   = (const float*)d_in[4];
    const float* W2   = (const float*)d_in[5];
    const float* b2   = (const float*)d_in[6];
    const float* Wf   = (const float*)d_in[7];
    const float* bf   = (const float*)d_in[8];
    const float* Wm   = (const float*)d_in[9];
    const float* bm   = (const float*)d_in[10];
    const float* Ws   = (const float*)d_in[11];
    const float* bs   = (const float*)d_in[12];
    const float* Wdec = (const float*)d_in[13];
    const float* bdec = (const float*)d_in[14];
    const float* Wg   = (const float*)d_in[15];
    const float* bg   = (const float*)d_in[16];
    const float* Wc   = (const float*)d_in[17];
    const float* bc   = (const float*)d_in[18];
    const float* Wv   = (const float*)d_in[19];
    const float* bv   = (const float*)d_in[20];
    const int*   ei   = (const int*)d_in[21];
    const int*   nei  = (const int*)d_in[22];
    float* out = (float*)d_out;

    float* out_ct   = out;              // [N,10]
    float* out_xdec = out + 100000;     // [N,2000]
    float* out_gae  = out + 20100000;   // scalar
    float* out_pw   = out + 20100001;   // [N,20000]

    // Launch #4 is k_dense1p (ncu captures the 4th launch).
    k_deg_init<<<(N_ + 255) / 256, 256>>>();                            // 1
    k_acc_zero<<<1, 32>>>();                                            // 2
    k_deg_acc<<<E_ / 256, 256>>>(ei, ew);                               // 3
    k_dense1p<<<dim3((N_ + D1_R - 1) / D1_R, D1_NC), 64>>>(x, W1);      // 4 <- profiled
    k_dense1f<<<(N_ * DAE0 + 255) / 256, 256>>>(b1);
    k_dinv<<<(N_ + 255) / 256, 256>>>();
    k_coef<<<E_ / 256, 256>>>(ei, ew);
    k_dense2<<<(N_ * DAE1 + 255) / 256, 256>>>(W2, b2);
    k_hW1<<<N_ * GAE0 / 256, 256>>>(Wf);
    k_gcn_init_h<<<N_ * GAE0 / 256, 256>>>(bf);
    k_gcn_edge_h<<<E_ * GAE0 / 256, 256>>>(ei);
    k_mls<<<(N_ * GAE1 + 255) / 256, 256>>>(Wm, Ws);
    k_gcn_init_muls<<<(N_ * GAE1 + 255) / 256, 256>>>(bm, bs);
    k_gcn_edge_muls<<<E_ * GAE1 / 256, 256>>>(ei);
    k_finalize<<<(N_ * GAE1 + 255) / 256, 256>>>(eps);
    k_ct<<<(N_ + 31) / 32, 320>>>(Wc, bc, out_ct);
    k_zg<<<N_ * FEAT / 256, 256>>>(Wg, bg);
    k_edge_loss<<<2 * E_ * 8 / 256, 256>>>(ei, nei, ew);
    k_gae<<<1, 1>>>(out_gae);
    k_xdec<<<dim3(4, N_ / 16), 256>>>(Wdec, bdec, out_xdec);
    k_pw<<<dim3(125, (N_ + 63) / 64), 128>>>(Wv, bv, out_pw);
}

// round 16
// speedup vs baseline: 1.0278x; 1.0278x over previous
#include <cuda_runtime.h>
#include <math.h>

#define N_   10000
#define P_   2000
#define CT_  10
#define E_   320000
#define DAE0 100
#define DAE1 20
#define GAE0 32
#define GAE1 20
#define FCAT 40
#define FEAT 64

#define D1_R     32
#define D1_PAIRS 16
#define D1_KC    250
#define D1_NC    8      // P_ / D1_KC

typedef unsigned long long u64;

// ---------------- scratch (no allocs allowed) ----------------
__device__ __align__(16) float g_h1[N_*DAE0];
__device__ __align__(16) float g_h1p[D1_NC][N_*DAE0];
__device__ __align__(16) float g_feat[N_*FCAT];
__device__ __align__(16) float g_deg[N_];
__device__ __align__(16) float g_dinv[N_];
__device__ __align__(16) float g_coef[E_];
__device__ __align__(16) float g_hW1[N_*GAE0];
__device__ __align__(16) float g_h[N_*GAE0];
__device__ __align__(16) float g_hWm[N_*GAE1];
__device__ __align__(16) float g_hWs[N_*GAE1];
__device__ __align__(16) float g_mu[N_*GAE1];
__device__ __align__(16) float g_ls[N_*GAE1];
__device__ __align__(16) float g_zg[N_*FEAT];
__device__ double g_acc[3];
// CSR (dst-sorted adjacency)
__device__ int   g_cnt[N_];
__device__ int   g_start[N_ + 1];
__device__ int   g_cur[N_];
__device__ int   g_esrc[E_];
__device__ float g_ecoef[E_];

// ---------------- f32x2 helpers ----------------
__device__ __forceinline__ u64 pk2(float lo, float hi) {
    u64 r;
    asm("mov.b64 %0, {%1, %2};" : "=l"(r) : "r"(__float_as_uint(lo)), "r"(__float_as_uint(hi)));
    return r;
}
__device__ __forceinline__ u64 dup2(float v) { return pk2(v, v); }
__device__ __forceinline__ void unpk(u64 v, float& lo, float& hi) {
    unsigned a, b;
    asm("mov.b64 {%0, %1}, %2;" : "=r"(a), "=r"(b) : "l"(v));
    lo = __uint_as_float(a); hi = __uint_as_float(b);
}
__device__ __forceinline__ u64 fma2(u64 a, u64 b, u64 c) {
    u64 d;
    asm("fma.rn.f32x2 %0, %1, %2, %3;" : "=l"(d) : "l"(a), "l"(b), "l"(c));
    return d;
}
__device__ __forceinline__ float celu_f(float v) { return v > 0.f ? v : expm1f(v); }

__device__ __forceinline__ void block_add(double* target, float v) {
    #pragma unroll
    for (int o = 16; o > 0; o >>= 1) v += __shfl_down_sync(0xffffffffu, v, o);
    __shared__ float ws[8];
    int w = threadIdx.x >> 5;
    if ((threadIdx.x & 31) == 0) ws[w] = v;
    __syncthreads();
    if (threadIdx.x == 0) {
        float s = 0.f;
        int nw = (blockDim.x + 31) >> 5;
        for (int i = 0; i < nw; i++) s += ws[i];
        atomicAdd(target, (double)s);
    }
}

// ---------------- setup kernels ----------------
__global__ void k_init0() {
    int i = blockIdx.x * blockDim.x + threadIdx.x;
    if (i < N_) { g_deg[i] = 1.f; g_cnt[i] = 0; }
    if (i < 3) g_acc[i] = 0.0;
}
__global__ void k_deg_cnt(const int* __restrict__ ei, const float* __restrict__ ew) {
    int e = blockIdx.x * blockDim.x + threadIdx.x;
    if (e < E_) {
        int d = ei[E_ + e];
        atomicAdd(&g_deg[d], ew[e]);
        atomicAdd(&g_cnt[d], 1);
    }
}
__global__ void k_dinv() {
    int i = blockIdx.x * blockDim.x + threadIdx.x;
    if (i < N_) g_dinv[i] = rsqrtf(g_deg[i]);
}
__global__ void k_coef(const int* __restrict__ ei, const float* __restrict__ ew) {
    int e = blockIdx.x * blockDim.x + threadIdx.x;
    if (e < E_) g_coef[e] = g_dinv[ei[e]] * g_dinv[ei[E_ + e]] * ew[e];
}

// exclusive scan of g_cnt -> g_start / g_cur (1 block, 1024 threads, 10 bins each)
__global__ void __launch_bounds__(1024) k_scan() {
    __shared__ int ps[1025];
    int t = threadIdx.x;
    int base = t * 10;
    int local[10];
    int s = 0;
    #pragma unroll
    for (int i = 0; i < 10; i++) {
        int b = base + i;
        int c = (b < N_) ? g_cnt[b] : 0;
        local[i] = s; s += c;
    }
    ps[t + 1] = s;
    if (t == 0) ps[0] = 0;
    __syncthreads();
    if (t == 0) for (int i = 1; i <= 1024; i++) ps[i] += ps[i - 1];
    __syncthreads();
    int off = ps[t];
    #pragma unroll
    for (int i = 0; i < 10; i++) {
        int b = base + i;
        if (b < N_) { g_start[b] = off + local[i]; g_cur[b] = off + local[i]; }
    }
    if (t == 0) g_start[N_] = E_;
}

__global__ void k_scatter(const int* __restrict__ ei) {
    int e = blockIdx.x * blockDim.x + threadIdx.x;
    if (e < E_) {
        int d = ei[E_ + e];
        int p = atomicAdd(&g_cur[d], 1);
        g_esrc[p]  = ei[e];
        g_ecoef[p] = g_coef[e];
    }
}

// ---------------- dense path ----------------
// dense1 partial: 32 rows x 250-k chunk; 2 output cols/thread; 64-thread blocks.
__global__ void __launch_bounds__(64) k_dense1p(const float* __restrict__ x,
                                                const float* __restrict__ W1) {
    __shared__ u64 sx[D1_PAIRS * D1_KC];   // 32 KB
    int r0 = blockIdx.x * D1_R;
    int c0 = blockIdx.y * D1_KC;
    for (int idx = threadIdx.x; idx < D1_PAIRS * D1_KC; idx += 64) {
        int p = idx / D1_KC, k = idx - p * D1_KC;
        int ra = r0 + 2 * p;
        int rb = ra + 1;
        if (ra > N_ - 1) ra = N_ - 1;
        if (rb > N_ - 1) rb = N_ - 1;
        sx[idx] = pk2(x[(size_t)ra * P_ + c0 + k], x[(size_t)rb * P_ + c0 + k]);
    }
    __syncthreads();
    int t = threadIdx.x;
    if (t >= 50) return;
    int j = t * 2;
    u64 accA[D1_PAIRS], accB[D1_PAIRS];
    #pragma unroll
    for (int p = 0; p < D1_PAIRS; p++) { accA[p] = 0ull; accB[p] = 0ull; }
    const float* w = W1 + (size_t)c0 * DAE0 + j;
    #pragma unroll 2
    for (int k = 0; k < D1_KC; k++) {
        float2 wv = *(const float2*)(w + (size_t)k * DAE0);
        u64 wa = dup2(wv.x);
        u64 wb = dup2(wv.y);
        #pragma unroll
        for (int p = 0; p < D1_PAIRS; p++) {
            u64 s = sx[p * D1_KC + k];
            accA[p] = fma2(s, wa, accA[p]);
            accB[p] = fma2(s, wb, accB[p]);
        }
    }
    float* outp = g_h1p[blockIdx.y];
    #pragma unroll
    for (int p = 0; p < D1_PAIRS; p++) {
        float loA, hiA, loB, hiB;
        unpk(accA[p], loA, hiA);
        unpk(accB[p], loB, hiB);
        int ra = r0 + 2 * p;
        if (ra < N_)     *(float2*)(outp + (size_t)ra * DAE0 + j)       = make_float2(loA, loB);
        if (ra + 1 < N_) *(float2*)(outp + (size_t)(ra + 1) * DAE0 + j) = make_float2(hiA, hiB);
    }
}

__global__ void k_dense1f(const float* __restrict__ b1) {
    int idx = blockIdx.x * blockDim.x + threadIdx.x;
    if (idx >= N_ * DAE0) return;
    int j = idx % DAE0;
    float s = b1[j];
    #pragma unroll
    for (int c = 0; c < D1_NC; c++) s += g_h1p[c][idx];
    g_h1[idx] = celu_f(s);
}

__global__ void k_dense2(const float* __restrict__ W2, const float* __restrict__ b2) {
    int idx = blockIdx.x * blockDim.x + threadIdx.x;
    if (idx >= N_ * DAE1) return;
    int n = idx / DAE1, j = idx - n * DAE1;
    float acc = b2[j];
    const float* h = g_h1 + n * DAE0;
    #pragma unroll 4
    for (int k = 0; k < DAE0; k++) acc += h[k] * W2[k * DAE1 + j];
    g_feat[n * FCAT + j] = celu_f(acc);
}

__global__ void k_hW1(const float* __restrict__ Wf) {
    int idx = blockIdx.x * blockDim.x + threadIdx.x;
    if (idx >= N_ * GAE0) return;
    int n = idx >> 5, f = idx & 31;
    float acc = 0.f;
    const float* fr = g_feat + n * FCAT;
    #pragma unroll
    for (int k = 0; k < DAE1; k++) acc += fr[k] * Wf[k * GAE0 + f];
    g_hW1[idx] = acc;
}

// ---------------- GCN gathers (no atomics) ----------------
// warp per node, lane = feature (F=32)
__global__ void __launch_bounds__(256) k_gather_h(const float* __restrict__ bf) {
    int warp = (blockIdx.x * blockDim.x + threadIdx.x) >> 5;
    int lane = threadIdx.x & 31;
    if (warp >= N_) return;
    int beg = g_start[warp], end = g_start[warp + 1];
    float acc = 0.f;
    #pragma unroll 4
    for (int i = beg; i < end; i++) {
        int s = g_esrc[i];
        float c = g_ecoef[i];
        acc = fmaf(c, g_hW1[s * GAE0 + lane], acc);
    }
    float di = g_dinv[warp];
    g_h[warp * GAE0 + lane] = acc + di * di * g_hW1[warp * GAE0 + lane] + bf[lane];
}

__global__ void k_mls(const float* __restrict__ Wm, const float* __restrict__ Ws) {
    int idx = blockIdx.x * blockDim.x + threadIdx.x;
    if (idx >= N_ * GAE1) return;
    int n = idx / GAE1, f = idx - n * GAE1;
    float am = 0.f, as = 0.f;
    const float* h = g_h + n * GAE0;
    #pragma unroll
    for (int k = 0; k < GAE0; k++) {
        float rh = fmaxf(h[k], 0.f);
        am += rh * Wm[k * GAE1 + f];
        as += rh * Ws[k * GAE1 + f];
    }
    g_hWm[idx] = am;
    g_hWs[idx] = as;
}

// warp per node, lanes 0..19 = feature; accumulates mu and ls together
__global__ void __launch_bounds__(256) k_gather_muls(const float* __restrict__ bm,
                                                     const float* __restrict__ bs) {
    int warp = (blockIdx.x * blockDim.x + threadIdx.x) >> 5;
    int lane = threadIdx.x & 31;
    if (warp >= N_ || lane >= GAE1) return;
    int beg = g_start[warp], end = g_start[warp + 1];
    float am = 0.f, as = 0.f;
    #pragma unroll 4
    for (int i = beg; i < end; i++) {
        int s = g_esrc[i];
        float c = g_ecoef[i];
        am = fmaf(c, g_hWm[s * GAE1 + lane], am);
        as = fmaf(c, g_hWs[s * GAE1 + lane], as);
    }
    float di = g_dinv[warp];
    float d2 = di * di;
    g_mu[warp * GAE1 + lane] = am + d2 * g_hWm[warp * GAE1 + lane] + bm[lane];
    g_ls[warp * GAE1 + lane] = as + d2 * g_hWs[warp * GAE1 + lane] + bs[lane];
}

__global__ void k_finalize(const float* __restrict__ eps) {
    int idx = blockIdx.x * blockDim.x + threadIdx.x;
    float t = 0.f;
    if (idx < N_ * GAE1) {
        int n = idx / GAE1, j = idx - n * GAE1;
        float m = g_mu[idx];
        float l = fminf(g_ls[idx], 10.f);
        float el = expf(l);
        g_feat[n * FCAT + DAE1 + j] = m + eps[idx] * el;
        t = 1.f + 2.f * l - m * m - el * el;
    }
    block_add(&g_acc[2], t);
}

// ---------------- heads ----------------
__global__ void __launch_bounds__(320) k_ct(const float* __restrict__ Wc,
                                            const float* __restrict__ bc,
                                            float* __restrict__ out) {
    __shared__ float fs[32 * FCAT];
    __shared__ float sv[32][CT_];
    int rbase = blockIdx.x * 32;
    for (int i = threadIdx.x; i < 32 * FCAT; i += 320) {
        int gi = rbase * FCAT + i;
        fs[i] = (gi < N_ * FCAT) ? g_feat[gi] : 0.f;
    }
    __syncthreads();
    int rl = threadIdx.x / CT_, c = threadIdx.x - rl * CT_;
    float acc = bc[c];
    const float* fr = fs + rl * FCAT;
    #pragma unroll
    for (int k = 0; k < FCAT; k++) acc += fr[k] * Wc[k * CT_ + c];
    float v = fmaxf(acc, 0.f);
    sv[rl][c] = v;
    __syncthreads();
    float s = 0.f;
    #pragma unroll
    for (int cc = 0; cc < CT_; cc++) s += sv[rl][cc];
    int n = rbase + rl;
    if (n < N_) out[n * CT_ + c] = v / (s + 1e-6f);
}

__global__ void k_zg(const float* __restrict__ Wg, const float* __restrict__ bg) {
    int idx = blockIdx.x * blockDim.x + threadIdx.x;
    if (idx >= N_ * FEAT) return;
    int n = idx >> 6, j = idx & 63;
    float acc = bg[j];
    const float* fr = g_feat + n * FCAT;
    #pragma unroll
    for (int k = 0; k < FCAT; k++) acc += fr[k] * Wg[k * FEAT + j];
    g_zg[idx] = fmaxf(acc, 0.f);
}

__global__ void __launch_bounds__(256) k_edge_loss(const int* __restrict__ ei,
                                                   const int* __restrict__ nei,
                                                   const float* __restrict__ ew) {
    int gid = blockIdx.x * 256 + threadIdx.x;
    int oct = gid >> 3, l8 = gid & 7;
    bool pos = oct < E_;
    int e = pos ? oct : oct - E_;
    const int* arr = pos ? ei : nei;
    int s = arr[e], d = arr[E_ + e];
    const float4* za = (const float4*)(g_zg + s * FEAT + l8 * 8);
    const float4* zb = (const float4*)(g_zg + d * FEAT + l8 * 8);
    float4 a0 = za[0], a1 = za[1], b0 = zb[0], b1 = zb[1];
    float dot = a0.x*b0.x + a0.y*b0.y + a0.z*b0.z + a0.w*b0.w
              + a1.x*b1.x + a1.y*b1.y + a1.z*b1.z + a1.w*b1.w;
    dot += __shfl_down_sync(0xffffffffu, dot, 4, 8);
    dot += __shfl_down_sync(0xffffffffu, dot, 2, 8);
    dot += __shfl_down_sync(0xffffffffu, dot, 1, 8);
    float val = 0.f;
    if (l8 == 0) {
        float sg = 1.f / (1.f + expf(-dot));
        if (pos) { float df = sg - ew[e]; val = df * df; }
        else     { val = sg * sg; }
    }
    block_add(&g_acc[pos ? 0 : 1], val);
}

__global__ void k_gae(float* __restrict__ out) {
    double kl_factor = -0.5 / ((double)N_ * (double)N_);
    out[0] = (float)(g_acc[0] / (double)E_ + g_acc[1] / (double)E_ + kl_factor * g_acc[2]);
}

__global__ void __launch_bounds__(256) k_xdec(const float* __restrict__ Wdec,
                                              const float* __restrict__ bdec,
                                              float* __restrict__ out) {
    __shared__ u64 fd[16 * FCAT];
    int rbase = blockIdx.y * 16;
    for (int i = threadIdx.x; i < 16 * FCAT; i += 256)
        fd[i] = dup2(g_feat[rbase * FCAT + i]);
    __syncthreads();
    int j2 = blockIdx.x * 256 + threadIdx.x;
    if (j2 >= P_ / 2) return;
    u64 wv[FCAT];
    const float* wb = Wdec + 2 * j2;
    #pragma unroll
    for (int k = 0; k < FCAT; k++) wv[k] = *(const u64*)(wb + k * P_);
    u64 bb = *(const u64*)(bdec + 2 * j2);
    for (int r = 0; r < 16; r++) {
        u64 a0 = bb, a1 = 0ull;
        const u64* fr = fd + r * FCAT;
        #pragma unroll
        for (int k = 0; k < FCAT; k += 2) {
            a0 = fma2(fr[k],     wv[k],     a0);
            a1 = fma2(fr[k + 1], wv[k + 1], a1);
        }
        float l0, h0, l1, h1;
        unpk(a0, l0, h0); unpk(a1, l1, h1);
        float2 res = make_float2(l0 + l1, h0 + h1);
        *(float2*)(out + (size_t)(rbase + r) * P_ + 2 * j2) = res;
    }
}

// pw head (round-14 form: 256 threads, 4 rows/thread)
__global__ void __launch_bounds__(256) k_pw(const float* __restrict__ Wv,
                                            const float* __restrict__ bv,
                                            float* __restrict__ out) {
    __shared__ float sm[64 * 160];
    int g  = threadIdx.x & 15;
    int rs = threadIdx.x >> 4;
    int rbase = blockIdx.y * 64;
    int cbase = blockIdx.x * 160;
    for (int i = threadIdx.x; i < 64 * FCAT; i += 256) {
        int gi = rbase * FCAT + i;
        sm[i] = (gi < N_ * FCAT) ? g_feat[gi] : 0.f;
    }
    __syncthreads();

    u64 acc[4][5];
    #pragma unroll
    for (int r = 0; r < 4; r++)
        #pragma unroll
        for (int c = 0; c < 5; c++) acc[r][c] = 0ull;

    const float* wbase = Wv + cbase + g * CT_;
    int r0 = rs * 4;
    #pragma unroll 4
    for (int k = 0; k < FCAT; k++) {
        const u64* wp = (const u64*)(wbase + (size_t)k * (P_ * CT_));
        u64 w0 = wp[0], w1 = wp[1], w2 = wp[2], w3 = wp[3], w4 = wp[4];
        u64 d0 = dup2(sm[(r0+0)*FCAT + k]);
        u64 d1 = dup2(sm[(r0+1)*FCAT + k]);
        u64 d2 = dup2(sm[(r0+2)*FCAT + k]);
        u64 d3 = dup2(sm[(r0+3)*FCAT + k]);
        acc[0][0]=fma2(d0,w0,acc[0][0]); acc[0][1]=fma2(d0,w1,acc[0][1]); acc[0][2]=fma2(d0,w2,acc[0][2]); acc[0][3]=fma2(d0,w3,acc[0][3]); acc[0][4]=fma2(d0,w4,acc[0][4]);
        acc[1][0]=fma2(d1,w0,acc[1][0]); acc[1][1]=fma2(d1,w1,acc[1][1]); acc[1][2]=fma2(d1,w2,acc[1][2]); acc[1][3]=fma2(d1,w3,acc[1][3]); acc[1][4]=fma2(d1,w4,acc[1][4]);
        acc[2][0]=fma2(d2,w0,acc[2][0]); acc[2][1]=fma2(d2,w1,acc[2][1]); acc[2][2]=fma2(d2,w2,acc[2][2]); acc[2][3]=fma2(d2,w3,acc[2][3]); acc[2][4]=fma2(d2,w4,acc[2][4]);
        acc[3][0]=fma2(d3,w0,acc[3][0]); acc[3][1]=fma2(d3,w1,acc[3][1]); acc[3][2]=fma2(d3,w2,acc[3][2]); acc[3][3]=fma2(d3,w3,acc[3][3]); acc[3][4]=fma2(d3,w4,acc[3][4]);
    }
    __syncthreads();

    float bvv[CT_];
    #pragma unroll
    for (int c = 0; c < CT_; c++) bvv[c] = bv[cbase + g * CT_ + c];

    #pragma unroll
    for (int r = 0; r < 4; r++) {
        float v[CT_];
        #pragma unroll
        for (int cp = 0; cp < 5; cp++) unpk(acc[r][cp], v[2*cp], v[2*cp+1]);
        float s = 0.f;
        #pragma unroll
        for (int c = 0; c < CT_; c++) { v[c] = fmaxf(v[c] + bvv[c], 0.f); s += v[c]; }
        float inv = 1.f / (s + 1e-6f);
        #pragma unroll
        for (int c = 0; c < CT_; c++) sm[(r0 + r) * 160 + g * CT_ + c] = v[c] * inv;
    }
    __syncthreads();
    for (int i = threadIdx.x; i < 64 * 160; i += 256) {
        int rl = i / 160, cl = i - rl * 160;
        int row = rbase + rl;
        if (row < N_) out[(size_t)row * (P_ * CT_) + cbase + cl] = sm[i];
    }
}

// ---------------- launch ----------------
extern "C" void kernel_launch(void* const* d_in, const int* in_sizes, int n_in,
                              void* d_out, int out_size) {
    const float* x    = (const float*)d_in[0];
    const float* ew   = (const float*)d_in[1];
    const float* eps  = (const float*)d_in[2];
    const float* W1   = (const float*)d_in[3];
    const float* b1   = (const float*)d_in[4];
    const float* W2   = (const float*)d_in[5];
    const float* b2   = (const float*)d_in[6];
    const float* Wf   = (const float*)d_in[7];
    const float* bf   = (const float*)d_in[8];
    const float* Wm   = (const float*)d_in[9];
    const float* bm   = (const float*)d_in[10];
    const float* Ws   = (const float*)d_in[11];
    const float* bs   = (const float*)d_in[12];
    const float* Wdec = (const float*)d_in[13];
    const float* bdec = (const float*)d_in[14];
    const float* Wg   = (const float*)d_in[15];
    const float* bg   = (const float*)d_in[16];
    const float* Wc   = (const float*)d_in[17];
    const float* bc   = (const float*)d_in[18];
    const float* Wv   = (const float*)d_in[19];
    const float* bv   = (const float*)d_in[20];
    const int*   ei   = (const int*)d_in[21];
    const int*   nei  = (const int*)d_in[22];
    float* out = (float*)d_out;

    float* out_ct   = out;              // [N,10]
    float* out_xdec = out + 100000;     // [N,2000]
    float* out_gae  = out + 20100000;   // scalar
    float* out_pw   = out + 20100001;   // [N,20000]

    // Launch #4 is k_dense1p (ncu captures the 4th launch).
    k_init0<<<(N_ + 255) / 256, 256>>>();                               // 1
    k_deg_cnt<<<E_ / 256, 256>>>(ei, ew);                               // 2
    k_scan<<<1, 1024>>>();                                              // 3
    k_dense1p<<<dim3((N_ + D1_R - 1) / D1_R, D1_NC), 64>>>(x, W1);      // 4 <- profiled
    k_dense1f<<<(N_ * DAE0 + 255) / 256, 256>>>(b1);
    k_dinv<<<(N_ + 255) / 256, 256>>>();
    k_coef<<<E_ / 256, 256>>>(ei, ew);
    k_scatter<<<E_ / 256, 256>>>(ei);
    k_dense2<<<(N_ * DAE1 + 255) / 256, 256>>>(W2, b2);
    k_hW1<<<N_ * GAE0 / 256, 256>>>(Wf);
    k_gather_h<<<(N_ * 32 + 255) / 256, 256>>>(bf);
    k_mls<<<(N_ * GAE1 + 255) / 256, 256>>>(Wm, Ws);
    k_gather_muls<<<(N_ * 32 + 255) / 256, 256>>>(bm, bs);
    k_finalize<<<(N_ * GAE1 + 255) / 256, 256>>>(eps);
    k_ct<<<(N_ + 31) / 32, 320>>>(Wc, bc, out_ct);
    k_zg<<<N_ * FEAT / 256, 256>>>(Wg, bg);
    k_edge_loss<<<2 * E_ * 8 / 256, 256>>>(ei, nei, ew);
    k_gae<<<1, 1>>>(out_gae);
    k_xdec<<<dim3(4, N_ / 16), 256>>>(Wdec, bdec, out_xdec);
    k_pw<<<dim3(125, (N_ + 63) / 64), 256>>>(Wv, bv, out_pw);
}

// round 17
// speedup vs baseline: 1.0738x; 1.0447x over previous
#include <cuda_runtime.h>
#include <math.h>

#define N_   10000
#define P_   2000
#define CT_  10
#define E_   320000
#define DAE0 100
#define DAE1 20
#define GAE0 32
#define GAE1 20
#define FCAT 40
#define FEAT 64

#define D1_R     32
#define D1_PAIRS 16
#define D1_KC    250
#define D1_NC    8      // P_ / D1_KC

typedef unsigned long long u64;

// ---------------- scratch (no allocs allowed) ----------------
__device__ __align__(16) float g_h1[N_*DAE0];
__device__ __align__(16) float g_h1p[D1_NC][N_*DAE0];
__device__ __align__(16) float g_feat[N_*FCAT];
__device__ __align__(16) float g_deg[N_];
__device__ __align__(16) float g_dinv[N_];
__device__ __align__(16) float g_hW1[N_*GAE0];
__device__ __align__(16) float g_h[N_*GAE0];
__device__ __align__(16) float g_hWm[N_*GAE1];
__device__ __align__(16) float g_hWs[N_*GAE1];
__device__ __align__(16) float g_mu[N_*GAE1];
__device__ __align__(16) float g_ls[N_*GAE1];
__device__ __align__(16) float g_zg[N_*FEAT];
__device__ double g_acc[3];
// CSR (dst-sorted adjacency)
__device__ int   g_cnt[N_];
__device__ int   g_start[N_ + 1];
__device__ int   g_cur[N_];
__device__ int   g_esrc[E_];
__device__ float g_ecoef[E_];

// ---------------- f32x2 helpers ----------------
__device__ __forceinline__ u64 pk2(float lo, float hi) {
    u64 r;
    asm("mov.b64 %0, {%1, %2};" : "=l"(r) : "r"(__float_as_uint(lo)), "r"(__float_as_uint(hi)));
    return r;
}
__device__ __forceinline__ u64 dup2(float v) { return pk2(v, v); }
__device__ __forceinline__ void unpk(u64 v, float& lo, float& hi) {
    unsigned a, b;
    asm("mov.b64 {%0, %1}, %2;" : "=r"(a), "=r"(b) : "l"(v));
    lo = __uint_as_float(a); hi = __uint_as_float(b);
}
__device__ __forceinline__ u64 fma2(u64 a, u64 b, u64 c) {
    u64 d;
    asm("fma.rn.f32x2 %0, %1, %2, %3;" : "=l"(d) : "l"(a), "l"(b), "l"(c));
    return d;
}
__device__ __forceinline__ float celu_f(float v) { return v > 0.f ? v : expm1f(v); }

__device__ __forceinline__ void block_add(double* target, float v) {
    #pragma unroll
    for (int o = 16; o > 0; o >>= 1) v += __shfl_down_sync(0xffffffffu, v, o);
    __shared__ float ws[8];
    int w = threadIdx.x >> 5;
    if ((threadIdx.x & 31) == 0) ws[w] = v;
    __syncthreads();
    if (threadIdx.x == 0) {
        float s = 0.f;
        int nw = (blockDim.x + 31) >> 5;
        for (int i = 0; i < nw; i++) s += ws[i];
        atomicAdd(target, (double)s);
    }
}

// ---------------- setup kernels ----------------
__global__ void k_init0() {
    int i = blockIdx.x * blockDim.x + threadIdx.x;
    if (i < N_) { g_deg[i] = 1.f; g_cnt[i] = 0; }
    if (i < 3) g_acc[i] = 0.0;
}
__global__ void k_deg_cnt(const int* __restrict__ ei, const float* __restrict__ ew) {
    int e = blockIdx.x * blockDim.x + threadIdx.x;
    if (e < E_) {
        int d = ei[E_ + e];
        atomicAdd(&g_deg[d], ew[e]);
        atomicAdd(&g_cnt[d], 1);
    }
}
// exclusive scan of g_cnt -> g_start/g_cur, plus dinv (1 block, 1024 threads)
__global__ void __launch_bounds__(1024) k_scan() {
    __shared__ int ps[1025];
    int t = threadIdx.x;
    int base = t * 10;
    int local[10];
    int s = 0;
    #pragma unroll
    for (int i = 0; i < 10; i++) {
        int b = base + i;
        int c = (b < N_) ? g_cnt[b] : 0;
        local[i] = s; s += c;
        if (b < N_) g_dinv[b] = rsqrtf(g_deg[b]);
    }
    ps[t + 1] = s;
    if (t == 0) ps[0] = 0;
    __syncthreads();
    if (t == 0) for (int i = 1; i <= 1024; i++) ps[i] += ps[i - 1];
    __syncthreads();
    int off = ps[t];
    #pragma unroll
    for (int i = 0; i < 10; i++) {
        int b = base + i;
        if (b < N_) { g_start[b] = off + local[i]; g_cur[b] = off + local[i]; }
    }
    if (t == 0) g_start[N_] = E_;
}
// fused coef + CSR scatter
__global__ void k_coef_scatter(const int* __restrict__ ei, const float* __restrict__ ew) {
    int e = blockIdx.x * blockDim.x + threadIdx.x;
    if (e < E_) {
        int s = ei[e], d = ei[E_ + e];
        float c = g_dinv[s] * g_dinv[d] * ew[e];
        int p = atomicAdd(&g_cur[d], 1);
        g_esrc[p]  = s;
        g_ecoef[p] = c;
    }
}

// ---------------- dense path ----------------
__global__ void __launch_bounds__(64) k_dense1p(const float* __restrict__ x,
                                                const float* __restrict__ W1) {
    __shared__ u64 sx[D1_PAIRS * D1_KC];   // 32 KB
    int r0 = blockIdx.x * D1_R;
    int c0 = blockIdx.y * D1_KC;
    for (int idx = threadIdx.x; idx < D1_PAIRS * D1_KC; idx += 64) {
        int p = idx / D1_KC, k = idx - p * D1_KC;
        int ra = r0 + 2 * p;
        int rb = ra + 1;
        if (ra > N_ - 1) ra = N_ - 1;
        if (rb > N_ - 1) rb = N_ - 1;
        sx[idx] = pk2(x[(size_t)ra * P_ + c0 + k], x[(size_t)rb * P_ + c0 + k]);
    }
    __syncthreads();
    int t = threadIdx.x;
    if (t >= 50) return;
    int j = t * 2;
    u64 accA[D1_PAIRS], accB[D1_PAIRS];
    #pragma unroll
    for (int p = 0; p < D1_PAIRS; p++) { accA[p] = 0ull; accB[p] = 0ull; }
    const float* w = W1 + (size_t)c0 * DAE0 + j;
    #pragma unroll 2
    for (int k = 0; k < D1_KC; k++) {
        float2 wv = *(const float2*)(w + (size_t)k * DAE0);
        u64 wa = dup2(wv.x);
        u64 wb = dup2(wv.y);
        #pragma unroll
        for (int p = 0; p < D1_PAIRS; p++) {
            u64 s = sx[p * D1_KC + k];
            accA[p] = fma2(s, wa, accA[p]);
            accB[p] = fma2(s, wb, accB[p]);
        }
    }
    float* outp = g_h1p[blockIdx.y];
    #pragma unroll
    for (int p = 0; p < D1_PAIRS; p++) {
        float loA, hiA, loB, hiB;
        unpk(accA[p], loA, hiA);
        unpk(accB[p], loB, hiB);
        int ra = r0 + 2 * p;
        if (ra < N_)     *(float2*)(outp + (size_t)ra * DAE0 + j)       = make_float2(loA, loB);
        if (ra + 1 < N_) *(float2*)(outp + (size_t)(ra + 1) * DAE0 + j) = make_float2(hiA, hiB);
    }
}

__global__ void k_dense1f(const float* __restrict__ b1) {
    int idx = blockIdx.x * blockDim.x + threadIdx.x;
    if (idx >= N_ * DAE0) return;
    int j = idx % DAE0;
    float s = b1[j];
    #pragma unroll
    for (int c = 0; c < D1_NC; c++) s += g_h1p[c][idx];
    g_h1[idx] = celu_f(s);
}

__global__ void k_dense2(const float* __restrict__ W2, const float* __restrict__ b2) {
    int idx = blockIdx.x * blockDim.x + threadIdx.x;
    if (idx >= N_ * DAE1) return;
    int n = idx / DAE1, j = idx - n * DAE1;
    float acc = b2[j];
    const float* h = g_h1 + n * DAE0;
    #pragma unroll 4
    for (int k = 0; k < DAE0; k++) acc += h[k] * W2[k * DAE1 + j];
    g_feat[n * FCAT + j] = celu_f(acc);
}

__global__ void k_hW1(const float* __restrict__ Wf) {
    int idx = blockIdx.x * blockDim.x + threadIdx.x;
    if (idx >= N_ * GAE0) return;
    int n = idx >> 5, f = idx & 31;
    float acc = 0.f;
    const float* fr = g_feat + n * FCAT;
    #pragma unroll
    for (int k = 0; k < DAE1; k++) acc += fr[k] * Wf[k * GAE0 + f];
    g_hW1[idx] = acc;
}

// ---------------- GCN gathers ----------------
__global__ void __launch_bounds__(256) k_gather_h(const float* __restrict__ bf) {
    int warp = (blockIdx.x * blockDim.x + threadIdx.x) >> 5;
    int lane = threadIdx.x & 31;
    if (warp >= N_) return;
    int beg = g_start[warp], end = g_start[warp + 1];
    float acc = 0.f;
    #pragma unroll 4
    for (int i = beg; i < end; i++) {
        int s = g_esrc[i];
        float c = g_ecoef[i];
        acc = fmaf(c, g_hW1[s * GAE0 + lane], acc);
    }
    float di = g_dinv[warp];
    g_h[warp * GAE0 + lane] = acc + di * di * g_hW1[warp * GAE0 + lane] + bf[lane];
}

__global__ void k_mls(const float* __restrict__ Wm, const float* __restrict__ Ws) {
    int idx = blockIdx.x * blockDim.x + threadIdx.x;
    if (idx >= N_ * GAE1) return;
    int n = idx / GAE1, f = idx - n * GAE1;
    float am = 0.f, as = 0.f;
    const float* h = g_h + n * GAE0;
    #pragma unroll
    for (int k = 0; k < GAE0; k++) {
        float rh = fmaxf(h[k], 0.f);
        am += rh * Wm[k * GAE1 + f];
        as += rh * Ws[k * GAE1 + f];
    }
    g_hWm[idx] = am;
    g_hWs[idx] = as;
}

__global__ void __launch_bounds__(256) k_gather_muls(const float* __restrict__ bm,
                                                     const float* __restrict__ bs) {
    int warp = (blockIdx.x * blockDim.x + threadIdx.x) >> 5;
    int lane = threadIdx.x & 31;
    if (warp >= N_ || lane >= GAE1) return;
    int beg = g_start[warp], end = g_start[warp + 1];
    float am = 0.f, as = 0.f;
    #pragma unroll 4
    for (int i = beg; i < end; i++) {
        int s = g_esrc[i];
        float c = g_ecoef[i];
        am = fmaf(c, g_hWm[s * GAE1 + lane], am);
        as = fmaf(c, g_hWs[s * GAE1 + lane], as);
    }
    float di = g_dinv[warp];
    float d2 = di * di;
    g_mu[warp * GAE1 + lane] = am + d2 * g_hWm[warp * GAE1 + lane] + bm[lane];
    g_ls[warp * GAE1 + lane] = as + d2 * g_hWs[warp * GAE1 + lane] + bs[lane];
}

__global__ void k_finalize(const float* __restrict__ eps) {
    int idx = blockIdx.x * blockDim.x + threadIdx.x;
    float t = 0.f;
    if (idx < N_ * GAE1) {
        int n = idx / GAE1, j = idx - n * GAE1;
        float m = g_mu[idx];
        float l = fminf(g_ls[idx], 10.f);
        float el = expf(l);
        g_feat[n * FCAT + DAE1 + j] = m + eps[idx] * el;
        t = 1.f + 2.f * l - m * m - el * el;
    }
    block_add(&g_acc[2], t);
}

// ---------------- heads ----------------
__global__ void __launch_bounds__(320) k_ct(const float* __restrict__ Wc,
                                            const float* __restrict__ bc,
                                            float* __restrict__ out) {
    __shared__ float fs[32 * FCAT];
    __shared__ float sv[32][CT_];
    int rbase = blockIdx.x * 32;
    for (int i = threadIdx.x; i < 32 * FCAT; i += 320) {
        int gi = rbase * FCAT + i;
        fs[i] = (gi < N_ * FCAT) ? g_feat[gi] : 0.f;
    }
    __syncthreads();
    int rl = threadIdx.x / CT_, c = threadIdx.x - rl * CT_;
    float acc = bc[c];
    const float* fr = fs + rl * FCAT;
    #pragma unroll
    for (int k = 0; k < FCAT; k++) acc += fr[k] * Wc[k * CT_ + c];
    float v = fmaxf(acc, 0.f);
    sv[rl][c] = v;
    __syncthreads();
    float s = 0.f;
    #pragma unroll
    for (int cc = 0; cc < CT_; cc++) s += sv[rl][cc];
    int n = rbase + rl;
    if (n < N_) out[n * CT_ + c] = v / (s + 1e-6f);
}

__global__ void k_zg(const float* __restrict__ Wg, const float* __restrict__ bg) {
    int idx = blockIdx.x * blockDim.x + threadIdx.x;
    if (idx >= N_ * FEAT) return;
    int n = idx >> 6, j = idx & 63;
    float acc = bg[j];
    const float* fr = g_feat + n * FCAT;
    #pragma unroll
    for (int k = 0; k < FCAT; k++) acc += fr[k] * Wg[k * FEAT + j];
    g_zg[idx] = fmaxf(acc, 0.f);
}

__global__ void __launch_bounds__(256) k_edge_loss(const int* __restrict__ ei,
                                                   const int* __restrict__ nei,
                                                   const float* __restrict__ ew) {
    int gid = blockIdx.x * 256 + threadIdx.x;
    int oct = gid >> 3, l8 = gid & 7;
    bool pos = oct < E_;
    int e = pos ? oct : oct - E_;
    const int* arr = pos ? ei : nei;
    int s = arr[e], d = arr[E_ + e];
    const float4* za = (const float4*)(g_zg + s * FEAT + l8 * 8);
    const float4* zb = (const float4*)(g_zg + d * FEAT + l8 * 8);
    float4 a0 = za[0], a1 = za[1], b0 = zb[0], b1 = zb[1];
    float dot = a0.x*b0.x + a0.y*b0.y + a0.z*b0.z + a0.w*b0.w
              + a1.x*b1.x + a1.y*b1.y + a1.z*b1.z + a1.w*b1.w;
    dot += __shfl_down_sync(0xffffffffu, dot, 4, 8);
    dot += __shfl_down_sync(0xffffffffu, dot, 2, 8);
    dot += __shfl_down_sync(0xffffffffu, dot, 1, 8);
    float val = 0.f;
    if (l8 == 0) {
        float sg = 1.f / (1.f + expf(-dot));
        if (pos) { float df = sg - ew[e]; val = df * df; }
        else     { val = sg * sg; }
    }
    block_add(&g_acc[pos ? 0 : 1], val);
}

__global__ void k_gae(float* __restrict__ out) {
    double kl_factor = -0.5 / ((double)N_ * (double)N_);
    out[0] = (float)(g_acc[0] / (double)E_ + g_acc[1] / (double)E_ + kl_factor * g_acc[2]);
}

__global__ void __launch_bounds__(256) k_xdec(const float* __restrict__ Wdec,
                                              const float* __restrict__ bdec,
                                              float* __restrict__ out) {
    __shared__ u64 fd[16 * FCAT];
    int rbase = blockIdx.y * 16;
    for (int i = threadIdx.x; i < 16 * FCAT; i += 256)
        fd[i] = dup2(g_feat[rbase * FCAT + i]);
    __syncthreads();
    int j2 = blockIdx.x * 256 + threadIdx.x;
    if (j2 >= P_ / 2) return;
    u64 wv[FCAT];
    const float* wb = Wdec + 2 * j2;
    #pragma unroll
    for (int k = 0; k < FCAT; k++) wv[k] = *(const u64*)(wb + k * P_);
    u64 bb = *(const u64*)(bdec + 2 * j2);
    for (int r = 0; r < 16; r++) {
        u64 a0 = bb, a1 = 0ull;
        const u64* fr = fd + r * FCAT;
        #pragma unroll
        for (int k = 0; k < FCAT; k += 2) {
            a0 = fma2(fr[k],     wv[k],     a0);
            a1 = fma2(fr[k + 1], wv[k + 1], a1);
        }
        float l0, h0, l1, h1;
        unpk(a0, l0, h0); unpk(a1, l1, h1);
        float2 res = make_float2(l0 + l1, h0 + h1);
        *(float2*)(out + (size_t)(rbase + r) * P_ + 2 * j2) = res;
    }
}

__global__ void __launch_bounds__(256) k_pw(const float* __restrict__ Wv,
                                            const float* __restrict__ bv,
                                            float* __restrict__ out) {
    __shared__ float sm[64 * 160];
    int g  = threadIdx.x & 15;
    int rs = threadIdx.x >> 4;
    int rbase = blockIdx.y * 64;
    int cbase = blockIdx.x * 160;
    for (int i = threadIdx.x; i < 64 * FCAT; i += 256) {
        int gi = rbase * FCAT + i;
        sm[i] = (gi < N_ * FCAT) ? g_feat[gi] : 0.f;
    }
    __syncthreads();

    u64 acc[4][5];
    #pragma unroll
    for (int r = 0; r < 4; r++)
        #pragma unroll
        for (int c = 0; c < 5; c++) acc[r][c] = 0ull;

    const float* wbase = Wv + cbase + g * CT_;
    int r0 = rs * 4;
    #pragma unroll 4
    for (int k = 0; k < FCAT; k++) {
        const u64* wp = (const u64*)(wbase + (size_t)k * (P_ * CT_));
        u64 w0 = wp[0], w1 = wp[1], w2 = wp[2], w3 = wp[3], w4 = wp[4];
        u64 d0 = dup2(sm[(r0+0)*FCAT + k]);
        u64 d1 = dup2(sm[(r0+1)*FCAT + k]);
        u64 d2 = dup2(sm[(r0+2)*FCAT + k]);
        u64 d3 = dup2(sm[(r0+3)*FCAT + k]);
        acc[0][0]=fma2(d0,w0,acc[0][0]); acc[0][1]=fma2(d0,w1,acc[0][1]); acc[0][2]=fma2(d0,w2,acc[0][2]); acc[0][3]=fma2(d0,w3,acc[0][3]); acc[0][4]=fma2(d0,w4,acc[0][4]);
        acc[1][0]=fma2(d1,w0,acc[1][0]); acc[1][1]=fma2(d1,w1,acc[1][1]); acc[1][2]=fma2(d1,w2,acc[1][2]); acc[1][3]=fma2(d1,w3,acc[1][3]); acc[1][4]=fma2(d1,w4,acc[1][4]);
        acc[2][0]=fma2(d2,w0,acc[2][0]); acc[2][1]=fma2(d2,w1,acc[2][1]); acc[2][2]=fma2(d2,w2,acc[2][2]); acc[2][3]=fma2(d2,w3,acc[2][3]); acc[2][4]=fma2(d2,w4,acc[2][4]);
        acc[3][0]=fma2(d3,w0,acc[3][0]); acc[3][1]=fma2(d3,w1,acc[3][1]); acc[3][2]=fma2(d3,w2,acc[3][2]); acc[3][3]=fma2(d3,w3,acc[3][3]); acc[3][4]=fma2(d3,w4,acc[3][4]);
    }
    __syncthreads();

    float bvv[CT_];
    #pragma unroll
    for (int c = 0; c < CT_; c++) bvv[c] = bv[cbase + g * CT_ + c];

    #pragma unroll
    for (int r = 0; r < 4; r++) {
        float v[CT_];
        #pragma unroll
        for (int cp = 0; cp < 5; cp++) unpk(acc[r][cp], v[2*cp], v[2*cp+1]);
        float s = 0.f;
        #pragma unroll
        for (int c = 0; c < CT_; c++) { v[c] = fmaxf(v[c] + bvv[c], 0.f); s += v[c]; }
        float inv = 1.f / (s + 1e-6f);
        #pragma unroll
        for (int c = 0; c < CT_; c++) sm[(r0 + r) * 160 + g * CT_ + c] = v[c] * inv;
    }
    __syncthreads();
    for (int i = threadIdx.x; i < 64 * 160; i += 256) {
        int rl = i / 160, cl = i - rl * 160;
        int row = rbase + rl;
        if (row < N_) out[(size_t)row * (P_ * CT_) + cbase + cl] = sm[i];
    }
}

// ---------------- launch (multi-stream fork/join, capture-safe) ----------------
extern "C" void kernel_launch(void* const* d_in, const int* in_sizes, int n_in,
                              void* d_out, int out_size) {
    const float* x    = (const float*)d_in[0];
    const float* ew   = (const float*)d_in[1];
    const float* eps  = (const float*)d_in[2];
    const float* W1   = (const float*)d_in[3];
    const float* b1   = (const float*)d_in[4];
    const float* W2   = (const float*)d_in[5];
    const float* b2   = (const float*)d_in[6];
    const float* Wf   = (const float*)d_in[7];
    const float* bf   = (const float*)d_in[8];
    const float* Wm   = (const float*)d_in[9];
    const float* bm   = (const float*)d_in[10];
    const float* Ws   = (const float*)d_in[11];
    const float* bs   = (const float*)d_in[12];
    const float* Wdec = (const float*)d_in[13];
    const float* bdec = (const float*)d_in[14];
    const float* Wg   = (const float*)d_in[15];
    const float* bg   = (const float*)d_in[16];
    const float* Wc   = (const float*)d_in[17];
    const float* bc   = (const float*)d_in[18];
    const float* Wv   = (const float*)d_in[19];
    const float* bv   = (const float*)d_in[20];
    const int*   ei   = (const int*)d_in[21];
    const int*   nei  = (const int*)d_in[22];
    float* out = (float*)d_out;

    float* out_ct   = out;              // [N,10]
    float* out_xdec = out + 100000;     // [N,2000]
    float* out_gae  = out + 20100000;   // scalar
    float* out_pw   = out + 20100001;   // [N,20000]

    // Streams/events created once on call 1 (not during capture).
    static cudaStream_t s1 = 0, s2 = 0, s3 = 0;
    static cudaEvent_t evA = 0, evB = 0, evC = 0, ev1 = 0, ev2 = 0, ev3 = 0;
    static bool init_done = false;
    if (!init_done) {
        cudaStreamCreateWithFlags(&s1, cudaStreamNonBlocking);
        cudaStreamCreateWithFlags(&s2, cudaStreamNonBlocking);
        cudaStreamCreateWithFlags(&s3, cudaStreamNonBlocking);
        cudaEventCreateWithFlags(&evA, cudaEventDisableTiming);
        cudaEventCreateWithFlags(&evB, cudaEventDisableTiming);
        cudaEventCreateWithFlags(&evC, cudaEventDisableTiming);
        cudaEventCreateWithFlags(&ev1, cudaEventDisableTiming);
        cudaEventCreateWithFlags(&ev2, cudaEventDisableTiming);
        cudaEventCreateWithFlags(&ev3, cudaEventDisableTiming);
        init_done = true;
    }
    cudaStream_t L = 0;   // legacy default stream (captured by harness)

    // --- edge/CSR chain on L, dense chain on s1 (concurrent) ---
    k_init0<<<(N_ + 255) / 256, 256, 0, L>>>();                         // 1
    cudaEventRecord(evA, L);
    k_deg_cnt<<<E_ / 256, 256, 0, L>>>(ei, ew);                         // 2
    k_scan<<<1, 1024, 0, L>>>();                                        // 3
    k_coef_scatter<<<E_ / 256, 256, 0, L>>>(ei, ew);                    // 4 <- profiled
    cudaStreamWaitEvent(s1, evA, 0);
    k_dense1p<<<dim3((N_ + D1_R - 1) / D1_R, D1_NC), 64, 0, s1>>>(x, W1);
    k_dense1f<<<(N_ * DAE0 + 255) / 256, 256, 0, s1>>>(b1);
    k_dense2<<<(N_ * DAE1 + 255) / 256, 256, 0, s1>>>(W2, b2);
    k_hW1<<<N_ * GAE0 / 256, 256, 0, s1>>>(Wf);
    cudaEventRecord(evB, s1);
    cudaStreamWaitEvent(L, evB, 0);

    // --- GCN chain on L ---
    k_gather_h<<<(N_ * 32 + 255) / 256, 256, 0, L>>>(bf);
    k_mls<<<(N_ * GAE1 + 255) / 256, 256, 0, L>>>(Wm, Ws);
    k_gather_muls<<<(N_ * 32 + 255) / 256, 256, 0, L>>>(bm, bs);
    k_finalize<<<(N_ * GAE1 + 255) / 256, 256, 0, L>>>(eps);
    cudaEventRecord(evC, L);

    // --- heads: fork onto s1/s2/s3 concurrent with pw on L ---
    cudaStreamWaitEvent(s1, evC, 0);
    k_ct<<<(N_ + 31) / 32, 320, 0, s1>>>(Wc, bc, out_ct);
    cudaEventRecord(ev1, s1);

    cudaStreamWaitEvent(s2, evC, 0);
    k_xdec<<<dim3(4, N_ / 16), 256, 0, s2>>>(Wdec, bdec, out_xdec);
    cudaEventRecord(ev2, s2);

    cudaStreamWaitEvent(s3, evC, 0);
    k_zg<<<N_ * FEAT / 256, 256, 0, s3>>>(Wg, bg);
    k_edge_loss<<<2 * E_ * 8 / 256, 256, 0, s3>>>(ei, nei, ew);
    k_gae<<<1, 1, 0, s3>>>(out_gae);
    cudaEventRecord(ev3, s3);

    k_pw<<<dim3(125, (N_ + 63) / 64), 256, 0, L>>>(Wv, bv, out_pw);

    cudaStreamWaitEvent(L, ev1, 0);
    cudaStreamWaitEvent(L, ev2, 0);
    cudaStreamWaitEvent(L, ev3, 0);
}